// round 10
// baseline (speedup 1.0000x reference)
#include <cuda_runtime.h>
#include <cstdint>

#define N_NODES   100000
#define N_EDGES   1200000
#define D         64
#define G_FEAT    128
#define N_GRAPHS  256
#define NB_SCAN   391            // ceil(N_NODES/256)

// Scratch (no allocations allowed -> __device__ globals)
__device__ float g_Weff[D];
__device__ float g_c;
// Pre-built tf32 B-fragment table: [stage][ntile][kstep][lane] as uint2
__device__ __align__(16) uint2 g_Bfrag[3 * 8 * 8 * 32];
// CSR
__device__ int g_deg[N_NODES];
__device__ int g_cur[N_NODES];
__device__ int g_off[N_NODES + 1];
__device__ int g_blk[512];
__device__ int g_csr[N_EDGES];

// ---------------------------------------------------------------------------
// helpers
// ---------------------------------------------------------------------------
__device__ __forceinline__ unsigned f2tf(float f) {
    unsigned u;
    asm("cvt.rna.tf32.f32 %0, %1;" : "=r"(u) : "f"(f));
    return u;
}

__device__ __forceinline__ void mma_tf32(float* d, const unsigned* a,
                                         const unsigned* b) {
    asm volatile(
        "mma.sync.aligned.m16n8k8.row.col.f32.tf32.tf32.f32 "
        "{%0,%1,%2,%3}, {%4,%5,%6,%7}, {%8,%9}, {%0,%1,%2,%3};"
        : "+f"(d[0]), "+f"(d[1]), "+f"(d[2]), "+f"(d[3])
        : "r"(a[0]), "r"(a[1]), "r"(a[2]), "r"(a[3]),
          "r"(b[0]), "r"(b[1]));
}

// ---------------------------------------------------------------------------
// Precompute W_eff = W_out @ W_pred, c = b_out . W_pred, init out = b_pred
// ---------------------------------------------------------------------------
__global__ void k_prep(const float* __restrict__ W_out,
                       const float* __restrict__ b_out,
                       const float* __restrict__ W_pred,
                       const float* __restrict__ b_pred,
                       float* __restrict__ out) {
    int t = threadIdx.x;
    if (t < D) {
        float s = 0.f;
        #pragma unroll 4
        for (int f = 0; f < G_FEAT; f++) s += W_out[t * G_FEAT + f] * W_pred[f];
        g_Weff[t] = s;
    }
    if (t == 0) {
        float s = 0.f;
        for (int f = 0; f < G_FEAT; f++) s += b_out[f] * W_pred[f];
        g_c = s;
    }
    if (t < N_GRAPHS) out[t] = b_pred[0];
}

// ---------------------------------------------------------------------------
// Build the per-lane tf32 B-fragment table (one-time).
// ---------------------------------------------------------------------------
__global__ void k_wprep(const float* __restrict__ W1,
                        const float* __restrict__ W2,
                        const float* __restrict__ W3) {
    int id = blockIdx.x * blockDim.x + threadIdx.x;
    if (id >= 3 * 8 * 8 * 32) return;
    int lane = id & 31;
    int k0   = (id >> 5) & 7;
    int t    = (id >> 8) & 7;
    int s    = id >> 11;
    const float* W = (s == 0) ? W1 : ((s == 1) ? W2 : W3);
    int g = lane >> 2, c = lane & 3;
    int n = 8 * t + g;
    int k = k0 * 8 + c;
    uint2 v;
    v.x = f2tf(W[k * 64 + n]);
    v.y = f2tf(W[(k + 4) * 64 + n]);
    g_Bfrag[id] = v;
}

// ---------------------------------------------------------------------------
// CSR build
// ---------------------------------------------------------------------------
__global__ void k_zero_deg() {
    int i = blockIdx.x * blockDim.x + threadIdx.x;
    if (i < N_NODES) { g_deg[i] = 0; g_cur[i] = 0; }
}

__global__ void k_count(const int* __restrict__ dst) {
    int e = blockIdx.x * blockDim.x + threadIdx.x;
    if (e < N_EDGES) atomicAdd(&g_deg[dst[e]], 1);
}

// block-level sums of 256 degrees each
__global__ void k_scan1() {
    __shared__ int s[256];
    int t = threadIdx.x;
    int i = blockIdx.x * 256 + t;
    int v = (i < N_NODES) ? g_deg[i] : 0;
    s[t] = v;
    __syncthreads();
    for (int off = 128; off > 0; off >>= 1) {
        if (t < off) s[t] += s[t + off];
        __syncthreads();
    }
    if (t == 0) g_blk[blockIdx.x] = s[0];
}

// exclusive scan of the NB_SCAN block sums (single block of 512)
__global__ void k_scan2() {
    __shared__ int s[512];
    int t = threadIdx.x;
    int v = (t < NB_SCAN) ? g_blk[t] : 0;
    s[t] = v;
    __syncthreads();
    for (int off = 1; off < 512; off <<= 1) {
        int x = (t >= off) ? s[t - off] : 0;
        __syncthreads();
        s[t] += x;
        __syncthreads();
    }
    if (t < NB_SCAN) g_blk[t] = s[t] - v;   // exclusive
}

// per-block exclusive scan + block offset -> g_off
__global__ void k_scan3() {
    __shared__ int s[256];
    int t = threadIdx.x;
    int i = blockIdx.x * 256 + t;
    int v = (i < N_NODES) ? g_deg[i] : 0;
    s[t] = v;
    __syncthreads();
    for (int off = 1; off < 256; off <<= 1) {
        int x = (t >= off) ? s[t - off] : 0;
        __syncthreads();
        s[t] += x;
        __syncthreads();
    }
    int base = g_blk[blockIdx.x];
    if (i < N_NODES) g_off[i] = base + s[t] - v;
    if (i == N_NODES) g_off[N_NODES] = N_EDGES;
}

__global__ void k_fill(const int* __restrict__ src,
                       const int* __restrict__ dst) {
    int e = blockIdx.x * blockDim.x + threadIdx.x;
    if (e >= N_EDGES) return;
    int d = dst[e];
    int p = atomicAdd(&g_cur[d], 1);
    g_csr[g_off[d] + p] = src[e];
}

// ---------------------------------------------------------------------------
// Fused node pipeline, v5: CSR gather in-kernel + tf32 mma.
//   agg = sum_{e in CSR[n]} x[src_e]          (smem, no gmem agg buffer)
//   h  = relu(agg@W1+b1) + relu(x@W2+b2)
//   h2 = relu(h@W3+b3);  s = h2 . W_eff;  out[gid[n]] += s + c
// CTA: 256 threads (8 warps), 128 nodes. Warp = 16 nodes (1 m16 tile) x N=64.
// ---------------------------------------------------------------------------
#define NT    256
#define NPC   128
#define SROW  68
#define SMEM_U32 (2 * NPC * SROW + 256)
#define SMEM_BYTES (SMEM_U32 * 4)

#define GEMM64T(tile, sB)                                                    \
    {                                                                        \
        _Pragma("unroll")                                                    \
        for (int k0 = 0; k0 < 8; k0++) {                                     \
            uint2 bfr[8];                                                    \
            _Pragma("unroll")                                                \
            for (int t = 0; t < 8; t++)                                      \
                bfr[t] = (sB)[(t * 8 + k0) * 32 + lane];                     \
            const unsigned* ap = (tile) + arow * SROW + k0 * 8 + c;          \
            unsigned afr[4];                                                 \
            afr[0] = ap[0];                                                  \
            afr[1] = ap[8 * SROW];                                           \
            afr[2] = ap[4];                                                  \
            afr[3] = ap[8 * SROW + 4];                                       \
            _Pragma("unroll")                                                \
            for (int t = 0; t < 8; t++)                                      \
                mma_tf32(acc[t], afr, (const unsigned*)&bfr[t]);             \
        }                                                                    \
    }

#define ZERO_ACC()                                                           \
    _Pragma("unroll")                                                        \
    for (int t = 0; t < 8; t++)                                              \
        _Pragma("unroll")                                                    \
        for (int i = 0; i < 4; i++) acc[t][i] = 0.f;

__global__ void __launch_bounds__(NT, 2) k_nodes(
    const float* __restrict__ nf, const int* __restrict__ gid,
    const float* __restrict__ b1, const float* __restrict__ b2,
    const float* __restrict__ b3, float* __restrict__ out) {

    extern __shared__ __align__(16) unsigned smu[];
    unsigned* sX = smu;                    // [128][SROW] x tile, later h tile
    unsigned* sG = sX + NPC * SROW;        // [128][SROW] agg tile
    float*    sb = (float*)(sG + NPC * SROW); // b1|b2|b3|we

    int tid  = threadIdx.x;
    int lane = tid & 31;
    int warp = tid >> 5;
    int g    = lane >> 2;
    int c    = lane & 3;
    int arow = warp * 16 + g;

    int node0 = blockIdx.x * NPC;

    if (tid < 64) {
        sb[tid]       = b1[tid];
        sb[64 + tid]  = b2[tid];
        sb[128 + tid] = b3[tid];
        sb[192 + tid] = g_Weff[tid];
    }

    // --- load x tile + CSR-gather agg tile; thread = half a node row ---
    {
        int r    = tid >> 1;
        int half = tid & 1;
        int node = node0 + r;
        bool ok  = node < N_NODES;
        const float4* xp = (const float4*)(nf + (size_t)node * D + half * 32);
        unsigned* dX = sX + r * SROW + half * 32;
        unsigned* dG = sG + r * SROW + half * 32;

        #pragma unroll
        for (int q = 0; q < 8; q++) {
            float4 v = ok ? xp[q] : make_float4(0.f, 0.f, 0.f, 0.f);
            *(uint4*)(dX + 4 * q) =
                make_uint4(f2tf(v.x), f2tf(v.y), f2tf(v.z), f2tf(v.w));
        }

        float a[32];
        #pragma unroll
        for (int i = 0; i < 32; i++) a[i] = 0.f;
        if (ok) {
            int beg = g_off[node];
            int end = g_off[node + 1];
            for (int e = beg; e < end; e++) {
                int s = g_csr[e];
                const float4* sp =
                    (const float4*)(nf + (size_t)s * D + half * 32);
                #pragma unroll
                for (int q = 0; q < 8; q++) {
                    float4 v = sp[q];
                    a[4*q+0] += v.x; a[4*q+1] += v.y;
                    a[4*q+2] += v.z; a[4*q+3] += v.w;
                }
            }
        }
        #pragma unroll
        for (int q = 0; q < 8; q++)
            *(uint4*)(dG + 4 * q) = make_uint4(f2tf(a[4*q+0]), f2tf(a[4*q+1]),
                                               f2tf(a[4*q+2]), f2tf(a[4*q+3]));
    }
    __syncthreads();

    const uint2* __restrict__ fr1 = g_Bfrag;           // W1 frags
    const uint2* __restrict__ fr2 = g_Bfrag + 2048;    // W2
    const uint2* __restrict__ fr3 = g_Bfrag + 4096;    // W3

    float acc[8][4];

    // ===== residual: r2 = relu(x @ W2 + b2) =====
    ZERO_ACC();
    GEMM64T(sX, fr2);

    float r2[8][4];
    #pragma unroll
    for (int t = 0; t < 8; t++) {
        int c0 = 8 * t + 2 * c, c1 = c0 + 1;
        r2[t][0] = fmaxf(acc[t][0] + sb[64 + c0], 0.f);
        r2[t][1] = fmaxf(acc[t][1] + sb[64 + c1], 0.f);
        r2[t][2] = fmaxf(acc[t][2] + sb[64 + c0], 0.f);
        r2[t][3] = fmaxf(acc[t][3] + sb[64 + c1], 0.f);
    }
    __syncthreads();   // all warps done reading sX (it becomes the h tile)

    // ===== stage 1: h = relu(agg @ W1 + b1) + r2, write h into sX =====
    ZERO_ACC();
    GEMM64T(sG, fr1);

    #pragma unroll
    for (int t = 0; t < 8; t++) {
        int c0 = 8 * t + 2 * c, c1 = c0 + 1;
        float h0 = fmaxf(acc[t][0] + sb[c0], 0.f) + r2[t][0];
        float h1 = fmaxf(acc[t][1] + sb[c1], 0.f) + r2[t][1];
        float h2 = fmaxf(acc[t][2] + sb[c0], 0.f) + r2[t][2];
        float h3 = fmaxf(acc[t][3] + sb[c1], 0.f) + r2[t][3];
        *(uint2*)(sX + arow * SROW + c0)       = make_uint2(f2tf(h0), f2tf(h1));
        *(uint2*)(sX + (arow + 8) * SROW + c0) = make_uint2(f2tf(h2), f2tf(h3));
    }
    __syncthreads();

    // ===== stage 2: h2 = relu(h @ W3 + b3);  s = h2 . W_eff =====
    ZERO_ACC();
    GEMM64T(sX, fr3);

    {
        float s0 = 0.f, s1 = 0.f;      // rows arow, arow+8
        #pragma unroll
        for (int t = 0; t < 8; t++) {
            int c0 = 8 * t + 2 * c, c1 = c0 + 1;
            float bb0 = sb[128 + c0], bb1 = sb[128 + c1];
            float w0  = sb[192 + c0], w1  = sb[192 + c1];
            s0 += fmaxf(acc[t][0] + bb0, 0.f) * w0
                + fmaxf(acc[t][1] + bb1, 0.f) * w1;
            s1 += fmaxf(acc[t][2] + bb0, 0.f) * w0
                + fmaxf(acc[t][3] + bb1, 0.f) * w1;
        }
        s0 += __shfl_xor_sync(0xffffffffu, s0, 1);
        s0 += __shfl_xor_sync(0xffffffffu, s0, 2);
        s1 += __shfl_xor_sync(0xffffffffu, s1, 1);
        s1 += __shfl_xor_sync(0xffffffffu, s1, 2);
        if (c == 0) {
            float cterm = g_c;
            int n0 = node0 + arow;
            if (n0 < N_NODES)     atomicAdd(&out[gid[n0]],     s0 + cterm);
            if (n0 + 8 < N_NODES) atomicAdd(&out[gid[n0 + 8]], s1 + cterm);
        }
    }
}

// ---------------------------------------------------------------------------
// kernel_launch
// inputs: 0 node_feats, 1 edge_feats(unused), 2 src, 3 dst, 4 graph_ids,
//         5 W_gcn, 6 b_gcn, 7 W_res, 8 b_res, 9 W_in, 10 b_in,
//         11 W_out, 12 b_out, 13 W_pred, 14 b_pred
// ---------------------------------------------------------------------------
extern "C" void kernel_launch(void* const* d_in, const int* in_sizes, int n_in,
                              void* d_out, int out_size) {
    const float* nf     = (const float*)d_in[0];
    const int*   src    = (const int*)d_in[2];
    const int*   dst    = (const int*)d_in[3];
    const int*   gids   = (const int*)d_in[4];
    const float* W_gcn  = (const float*)d_in[5];
    const float* b_gcn  = (const float*)d_in[6];
    const float* W_res  = (const float*)d_in[7];
    const float* b_res  = (const float*)d_in[8];
    const float* W_in   = (const float*)d_in[9];
    const float* b_in   = (const float*)d_in[10];
    const float* W_out  = (const float*)d_in[11];
    const float* b_out  = (const float*)d_in[12];
    const float* W_pred = (const float*)d_in[13];
    const float* b_pred = (const float*)d_in[14];
    float* out = (float*)d_out;

    cudaFuncSetAttribute(k_nodes, cudaFuncAttributeMaxDynamicSharedMemorySize,
                         SMEM_BYTES);

    k_prep<<<1, 256>>>(W_out, b_out, W_pred, b_pred, out);
    k_wprep<<<48, 128>>>(W_gcn, W_res, W_in);

    // CSR build
    k_zero_deg<<<(N_NODES + 255) / 256, 256>>>();
    k_count<<<(N_EDGES + 255) / 256, 256>>>(dst);
    k_scan1<<<NB_SCAN, 256>>>();
    k_scan2<<<1, 512>>>();
    k_scan3<<<NB_SCAN, 256>>>();
    k_fill<<<(N_EDGES + 255) / 256, 256>>>(src, dst);

    {
        int grid = (N_NODES + NPC - 1) / NPC;
        k_nodes<<<grid, NT, SMEM_BYTES>>>(nf, gids, b_gcn, b_res, b_in, out);
    }
}

// round 14
// speedup vs baseline: 1.2816x; 1.2816x over previous
#include <cuda_runtime.h>
#include <cstdint>

#define N_NODES   100000
#define N_EDGES   1200000
#define D         64
#define G_FEAT    128
#define N_GRAPHS  256

// Scratch (no allocations allowed -> __device__ globals)
__device__ __align__(16) float g_agg[N_NODES * D];   // 25.6 MB
__device__ float g_Weff[D];
__device__ float g_c;
// Pre-built tf32 B-fragment table: [stage][ntile][kstep][lane] as uint2
// frag.x = tf32(W[(k0*8+c)*64 + n]), frag.y = tf32(W[(k0*8+c+4)*64 + n])
__device__ __align__(16) uint2 g_Bfrag[3 * 8 * 8 * 32];

// ---------------------------------------------------------------------------
// helpers
// ---------------------------------------------------------------------------
__device__ __forceinline__ unsigned f2tf(float f) {
    unsigned u;
    asm("cvt.rna.tf32.f32 %0, %1;" : "=r"(u) : "f"(f));
    return u;
}

__device__ __forceinline__ void mma_tf32(float* d, const unsigned* a,
                                         const unsigned* b) {
    asm volatile(
        "mma.sync.aligned.m16n8k8.row.col.f32.tf32.tf32.f32 "
        "{%0,%1,%2,%3}, {%4,%5,%6,%7}, {%8,%9}, {%0,%1,%2,%3};"
        : "+f"(d[0]), "+f"(d[1]), "+f"(d[2]), "+f"(d[3])
        : "r"(a[0]), "r"(a[1]), "r"(a[2]), "r"(a[3]),
          "r"(b[0]), "r"(b[1]));
}

// ---------------------------------------------------------------------------
// Zero the aggregation buffer
// ---------------------------------------------------------------------------
__global__ void k_zero_agg() {
    int i = blockIdx.x * blockDim.x + threadIdx.x;
    if (i < (N_NODES * D) / 4) {
        ((float4*)g_agg)[i] = make_float4(0.f, 0.f, 0.f, 0.f);
    }
}

// ---------------------------------------------------------------------------
// Precompute W_eff = W_out @ W_pred, c = b_out . W_pred, init out = b_pred
// ---------------------------------------------------------------------------
__global__ void k_prep(const float* __restrict__ W_out,
                       const float* __restrict__ b_out,
                       const float* __restrict__ W_pred,
                       const float* __restrict__ b_pred,
                       float* __restrict__ out) {
    int t = threadIdx.x;
    if (t < D) {
        float s = 0.f;
        #pragma unroll 4
        for (int f = 0; f < G_FEAT; f++) s += W_out[t * G_FEAT + f] * W_pred[f];
        g_Weff[t] = s;
    }
    if (t == 0) {
        float s = 0.f;
        for (int f = 0; f < G_FEAT; f++) s += b_out[f] * W_pred[f];
        g_c = s;
    }
    if (t < N_GRAPHS) out[t] = b_pred[0];
}

// ---------------------------------------------------------------------------
// Build the per-lane tf32 B-fragment table (one-time).
// ---------------------------------------------------------------------------
__global__ void k_wprep(const float* __restrict__ W1,
                        const float* __restrict__ W2,
                        const float* __restrict__ W3) {
    int id = blockIdx.x * blockDim.x + threadIdx.x;
    if (id >= 3 * 8 * 8 * 32) return;
    int lane = id & 31;
    int k0   = (id >> 5) & 7;
    int t    = (id >> 8) & 7;
    int s    = id >> 11;
    const float* W = (s == 0) ? W1 : ((s == 1) ? W2 : W3);
    int g = lane >> 2, c = lane & 3;
    int n = 8 * t + g;
    int k = k0 * 8 + c;
    uint2 v;
    v.x = f2tf(W[k * 64 + n]);
    v.y = f2tf(W[(k + 4) * 64 + n]);
    g_Bfrag[id] = v;
}

// ---------------------------------------------------------------------------
// Edge scatter: agg[dst] += node_feats[src]. 16 threads/edge, one
// red.global.add.v4.f32 each (REDG-lane-rate bound, ~71us; proven round 8).
// ---------------------------------------------------------------------------
__global__ void __launch_bounds__(256) k_edges(const float* __restrict__ nf,
                                               const int* __restrict__ src,
                                               const int* __restrict__ dst) {
    long long t = (long long)blockIdx.x * blockDim.x + threadIdx.x;
    int e = (int)(t >> 4);
    int j = (int)(t & 15);
    if (e >= N_EDGES) return;
    int s = src[e];
    int d = dst[e];
    float4 v = ((const float4*)(nf + (size_t)s * D))[j];
    float* p = g_agg + (size_t)d * D + j * 4;
    asm volatile("red.global.add.v4.f32 [%0], {%1, %2, %3, %4};"
                 :: "l"(p), "f"(v.x), "f"(v.y), "f"(v.z), "f"(v.w)
                 : "memory");
}

// ---------------------------------------------------------------------------
// Fused node pipeline, v6: tf32 mma, fully warp-local (ZERO __syncthreads).
//   h  = relu(agg@W1+b1) + relu(x@W2+b2)
//   h2 = relu(h@W3+b3);  s = h2 . W_eff;  out[gid[n]] += s + c
// CTA: 256 threads (8 warps), 128 nodes. Warp = 16 nodes (1 m16 tile) x N=64.
// Each warp loads ONLY its own 16 rows (coalesced: 16 lanes per row ->
// 4 lines per LDG.128), consumes only its own rows, writes h to its own
// rows. Biases/Weff read via __ldg (L1-hot) -> no cross-warp smem deps.
// launch_bounds(256,3) -> 24 warps/SM.
// ---------------------------------------------------------------------------
#define NT    256
#define NPC   128
#define SROW  68
#define SMEM_U32 (2 * NPC * SROW)
#define SMEM_BYTES (SMEM_U32 * 4)

#define GEMM64T(tile, sB)                                                    \
    {                                                                        \
        _Pragma("unroll")                                                    \
        for (int k0 = 0; k0 < 8; k0++) {                                     \
            uint2 bfr[8];                                                    \
            _Pragma("unroll")                                                \
            for (int t = 0; t < 8; t++)                                      \
                bfr[t] = (sB)[(t * 8 + k0) * 32 + lane];                     \
            const unsigned* ap = (tile) + arow * SROW + k0 * 8 + c;          \
            unsigned afr[4];                                                 \
            afr[0] = ap[0];                                                  \
            afr[1] = ap[8 * SROW];                                           \
            afr[2] = ap[4];                                                  \
            afr[3] = ap[8 * SROW + 4];                                       \
            _Pragma("unroll")                                                \
            for (int t = 0; t < 8; t++)                                      \
                mma_tf32(acc[t], afr, (const unsigned*)&bfr[t]);             \
        }                                                                    \
    }

#define ZERO_ACC()                                                           \
    _Pragma("unroll")                                                        \
    for (int t = 0; t < 8; t++)                                              \
        _Pragma("unroll")                                                    \
        for (int i = 0; i < 4; i++) acc[t][i] = 0.f;

__global__ void __launch_bounds__(NT, 3) k_nodes(
    const float* __restrict__ nf, const int* __restrict__ gid,
    const float* __restrict__ b1, const float* __restrict__ b2,
    const float* __restrict__ b3, float* __restrict__ out) {

    extern __shared__ __align__(16) unsigned smu[];
    unsigned* sX = smu;                    // [128][SROW] x tile, later h tile
    unsigned* sG = sX + NPC * SROW;        // [128][SROW] agg tile

    int tid  = threadIdx.x;
    int lane = tid & 31;
    int warp = tid >> 5;
    int g    = lane >> 2;
    int c    = lane & 3;
    int arow = warp * 16 + g;

    int node0 = blockIdx.x * NPC;

    // --- per-warp coalesced load of the warp's own 16 rows (x and agg) ---
    #pragma unroll
    for (int it = 0; it < 8; it++) {
        int idx  = it * 32 + lane;           // 0..255 over the warp's tile
        int row  = warp * 16 + (idx >> 4);   // rows 16w .. 16w+15
        int q    = idx & 15;                 // float4 chunk within row
        int nrow = node0 + row;
        bool ok  = nrow < N_NODES;
        const float4* xp = (const float4*)(nf    + (size_t)nrow * D);
        const float4* gp = (const float4*)(g_agg + (size_t)nrow * D);
        float4 vx = ok ? xp[q] : make_float4(0.f, 0.f, 0.f, 0.f);
        float4 va = ok ? gp[q] : make_float4(0.f, 0.f, 0.f, 0.f);
        *(uint4*)(sX + row * SROW + 4 * q) =
            make_uint4(f2tf(vx.x), f2tf(vx.y), f2tf(vx.z), f2tf(vx.w));
        *(uint4*)(sG + row * SROW + 4 * q) =
            make_uint4(f2tf(va.x), f2tf(va.y), f2tf(va.z), f2tf(va.w));
    }
    __syncwarp();

    const uint2* __restrict__ fr1 = g_Bfrag;           // W1 frags
    const uint2* __restrict__ fr2 = g_Bfrag + 2048;    // W2
    const uint2* __restrict__ fr3 = g_Bfrag + 4096;    // W3

    float acc[8][4];

    // ===== stage 1: hr = relu(agg @ W1 + b1), kept in registers =====
    ZERO_ACC();
    GEMM64T(sG, fr1);

    float hr[8][4];
    #pragma unroll
    for (int t = 0; t < 8; t++) {
        int c0 = 8 * t + 2 * c;
        float2 bb = __ldg((const float2*)(b1 + c0));
        hr[t][0] = fmaxf(acc[t][0] + bb.x, 0.f);
        hr[t][1] = fmaxf(acc[t][1] + bb.y, 0.f);
        hr[t][2] = fmaxf(acc[t][2] + bb.x, 0.f);
        hr[t][3] = fmaxf(acc[t][3] + bb.y, 0.f);
    }

    // ===== stage 2: h = hr + relu(x @ W2 + b2), write h into own sX rows ===
    ZERO_ACC();
    GEMM64T(sX, fr2);

    #pragma unroll
    for (int t = 0; t < 8; t++) {
        int c0 = 8 * t + 2 * c;
        float2 bb = __ldg((const float2*)(b2 + c0));
        float h0 = hr[t][0] + fmaxf(acc[t][0] + bb.x, 0.f);
        float h1 = hr[t][1] + fmaxf(acc[t][1] + bb.y, 0.f);
        float h2 = hr[t][2] + fmaxf(acc[t][2] + bb.x, 0.f);
        float h3 = hr[t][3] + fmaxf(acc[t][3] + bb.y, 0.f);
        *(uint2*)(sX + arow * SROW + c0)       = make_uint2(f2tf(h0), f2tf(h1));
        *(uint2*)(sX + (arow + 8) * SROW + c0) = make_uint2(f2tf(h2), f2tf(h3));
    }
    __syncwarp();

    // ===== stage 3: h2 = relu(h @ W3 + b3);  s = h2 . W_eff =====
    ZERO_ACC();
    GEMM64T(sX, fr3);

    {
        float s0 = 0.f, s1 = 0.f;      // rows arow, arow+8
        #pragma unroll
        for (int t = 0; t < 8; t++) {
            int c0 = 8 * t + 2 * c;
            float2 bb = __ldg((const float2*)(b3 + c0));
            float2 ww = __ldg((const float2*)(g_Weff + c0));
            s0 += fmaxf(acc[t][0] + bb.x, 0.f) * ww.x
                + fmaxf(acc[t][1] + bb.y, 0.f) * ww.y;
            s1 += fmaxf(acc[t][2] + bb.x, 0.f) * ww.x
                + fmaxf(acc[t][3] + bb.y, 0.f) * ww.y;
        }
        s0 += __shfl_xor_sync(0xffffffffu, s0, 1);
        s0 += __shfl_xor_sync(0xffffffffu, s0, 2);
        s1 += __shfl_xor_sync(0xffffffffu, s1, 1);
        s1 += __shfl_xor_sync(0xffffffffu, s1, 2);
        if (c == 0) {
            float cterm = g_c;
            int n0 = node0 + arow;
            if (n0 < N_NODES)     atomicAdd(&out[gid[n0]],     s0 + cterm);
            if (n0 + 8 < N_NODES) atomicAdd(&out[gid[n0 + 8]], s1 + cterm);
        }
    }
}

// ---------------------------------------------------------------------------
// kernel_launch
// inputs: 0 node_feats, 1 edge_feats(unused), 2 src, 3 dst, 4 graph_ids,
//         5 W_gcn, 6 b_gcn, 7 W_res, 8 b_res, 9 W_in, 10 b_in,
//         11 W_out, 12 b_out, 13 W_pred, 14 b_pred
// ---------------------------------------------------------------------------
extern "C" void kernel_launch(void* const* d_in, const int* in_sizes, int n_in,
                              void* d_out, int out_size) {
    const float* nf     = (const float*)d_in[0];
    const int*   src    = (const int*)d_in[2];
    const int*   dst    = (const int*)d_in[3];
    const int*   gids   = (const int*)d_in[4];
    const float* W_gcn  = (const float*)d_in[5];
    const float* b_gcn  = (const float*)d_in[6];
    const float* W_res  = (const float*)d_in[7];
    const float* b_res  = (const float*)d_in[8];
    const float* W_in   = (const float*)d_in[9];
    const float* b_in   = (const float*)d_in[10];
    const float* W_out  = (const float*)d_in[11];
    const float* b_out  = (const float*)d_in[12];
    const float* W_pred = (const float*)d_in[13];
    const float* b_pred = (const float*)d_in[14];
    float* out = (float*)d_out;

    cudaFuncSetAttribute(k_nodes, cudaFuncAttributeMaxDynamicSharedMemorySize,
                         SMEM_BYTES);

    k_zero_agg<<<(N_NODES * D / 4 + 255) / 256, 256>>>();
    k_prep<<<1, 256>>>(W_out, b_out, W_pred, b_pred, out);
    k_wprep<<<48, 128>>>(W_gcn, W_res, W_in);
    {
        long long total = (long long)N_EDGES * 16;
        int grid = (int)((total + 255) / 256);
        k_edges<<<grid, 256>>>(nf, src, dst);
    }
    {
        int grid = (N_NODES + NPC - 1) / NPC;
        k_nodes<<<grid, NT, SMEM_BYTES>>>(nf, gids, b_gcn, b_res, b_in, out);
    }
}